// round 1
// baseline (speedup 1.0000x reference)
#include <cuda_runtime.h>

// Problem constants
#define IHW   32
#define IC    8
#define OC    16
#define PP    5
#define IDIM  72            // IC*3*3
#define NROWS 8192          // N*OH*OW = 8*32*32
#define PSTRIDE 28          // params per (i,o), padded to 7 float4

// Precomputed per-(i,o) parameters, laid out [i][o][28]:
//  [0]=l2, [1..5]=z, [6..10]=alpha, [11..25]=Linv (lower tri row-major), [26..27]=pad
__device__ float g_params[IDIM * OC * PSTRIDE];

// ---------------------------------------------------------------------------
// Kernel 1: per-neuron precompute (fp64 Cholesky for robustness; 1152 threads)
// ---------------------------------------------------------------------------
__global__ void gp_precompute(const float* __restrict__ z,
                              const float* __restrict__ h,
                              const float* __restrict__ raw_l)
{
    int idx = blockIdx.x * blockDim.x + threadIdx.x;
    if (idx >= OC * IDIM) return;
    int o = idx / IDIM;
    int i = idx % IDIM;

    double zz[PP], hh[PP];
#pragma unroll
    for (int p = 0; p < PP; p++) {
        zz[p] = (double)z[(o * IDIM + i) * PP + p];
        hh[p] = (double)h[(o * IDIM + i) * PP + p];
    }
    double rl = (double)raw_l[o * IDIM + i];
    double l  = log1p(exp(rl));        // softplus
    double l2 = l * l;

    // K = exp(-0.5 dz^2 / l2) + 1e-4 I
    double K[PP][PP];
#pragma unroll
    for (int a = 0; a < PP; a++) {
#pragma unroll
        for (int b = 0; b < PP; b++) {
            double d = zz[a] - zz[b];
            K[a][b] = exp(-0.5 * d * d / l2);
        }
        K[a][a] += 1e-4;
    }

    // Cholesky: K = L L^T (lower)
    double L[PP][PP];
#pragma unroll
    for (int a = 0; a < PP; a++) {
        double s = K[a][a];
        for (int k = 0; k < a; k++) s -= L[a][k] * L[a][k];
        L[a][a] = sqrt(s);
        for (int b = a + 1; b < PP; b++) {
            double t = K[b][a];
            for (int k = 0; k < a; k++) t -= L[b][k] * L[a][k];
            L[b][a] = t / L[a][a];
        }
    }

    // Linv (lower triangular inverse of L)
    double Li[PP][PP];
#pragma unroll
    for (int c = 0; c < PP; c++) {
        for (int a = 0; a < PP; a++) {
            if (a < c) { Li[a][c] = 0.0; continue; }
            double t = (a == c) ? 1.0 : 0.0;
            for (int k = c; k < a; k++) t -= L[a][k] * Li[k][c];
            Li[a][c] = t / L[a][a];
        }
    }

    // alpha = K^{-1} h via two triangular solves
    double t1[PP];
#pragma unroll
    for (int a = 0; a < PP; a++) {
        double t = hh[a];
        for (int k = 0; k < a; k++) t -= L[a][k] * t1[k];
        t1[a] = t / L[a][a];
    }
    double alpha[PP];
    for (int a = PP - 1; a >= 0; a--) {
        double t = t1[a];
        for (int k = a + 1; k < PP; k++) t -= L[k][a] * alpha[k];
        alpha[a] = t / L[a][a];
    }

    float* pp = &g_params[(i * OC + o) * PSTRIDE];
    pp[0] = (float)l2;
#pragma unroll
    for (int p = 0; p < PP; p++) pp[1 + p] = (float)zz[p];
#pragma unroll
    for (int p = 0; p < PP; p++) pp[6 + p] = (float)alpha[p];
    int k = 11;
#pragma unroll
    for (int a = 0; a < PP; a++)
#pragma unroll
        for (int b = 0; b <= a; b++) pp[k++] = (float)Li[a][b];
    pp[26] = 0.0f;
    pp[27] = 0.0f;
}

// ---------------------------------------------------------------------------
// Kernel 2: main GP moment propagation.
// CTA = 256 threads = 16 pixels (r) x 16 output channels (o).
// ---------------------------------------------------------------------------
__global__ __launch_bounds__(256) void gp_main(const float* __restrict__ xm,
                                               const float* __restrict__ xv,
                                               float* __restrict__ out)
{
    __shared__ float mu_s[IDIM * 16];
    __shared__ float s2_s[IDIM * 16];

    const int tid = threadIdx.x;
    const int row_base = blockIdx.x * 16;   // 16 consecutive pixels, same (n, oh)

    // ---- stage im2col patch means/vars for the 16 pixels into smem ----
    {
        const int n   = row_base >> 10;
        const int oh  = (row_base >> 5) & 31;
        const int ow0 = row_base & 31;      // 0 or 16
        for (int idx = tid; idx < IDIM * 16; idx += 256) {
            int r  = idx & 15;
            int i  = idx >> 4;
            int c  = i / 9;
            int k9 = i - c * 9;
            int kh = k9 / 3;
            int kw = k9 - kh * 3;
            int y  = oh + kh - 1;
            int x  = ow0 + r + kw - 1;
            float m = 0.0f, v = 0.0f;
            if ((unsigned)y < 32u && (unsigned)x < 32u) {
                int g = ((n * IHW + y) * IHW + x) * IC + c;
                m = xm[g];
                v = xv[g];
            }
            mu_s[i * 16 + r] = m;
            s2_s[i * 16 + r] = v;
        }
    }
    __syncthreads();

    const int o = tid & 15;
    const int r = tid >> 4;
    const float4* __restrict__ pbase = (const float4*)g_params;

    float accm = 0.0f;
    float accv = 0.0f;

#pragma unroll 2
    for (int i = 0; i < IDIM; i++) {
        const float mu = mu_s[i * 16 + r];
        const float s2 = s2_s[i * 16 + r];

        const float4* pp = pbase + (i * OC + o) * 7;
        float4 p0 = pp[0];   // l2, z0, z1, z2
        float4 p1 = pp[1];   // z3, z4, a0, a1
        float4 p2 = pp[2];   // a2, a3, a4, L00
        float4 p3 = pp[3];   // L10, L11, L20, L21
        float4 p4 = pp[4];   // L22, L30, L31, L32
        float4 p5 = pp[5];   // L33, L40, L41, L42
        float4 p6 = pp[6];   // L43, L44, pad, pad

        float l2 = p0.x;
        float d  = l2 + s2;
        float inv_d;
        asm("rcp.approx.ftz.f32 %0, %1;" : "=f"(inv_d) : "f"(d));
        float cc  = -0.7213475204f * inv_d;   // -0.5 * log2(e) / d
        float l2d = l2 * inv_d;               // = s^2 (no sqrt needed for var)

        float df, e0, e1, e2, e3, e4;
        df = mu - p0.y; asm("ex2.approx.ftz.f32 %0, %1;" : "=f"(e0) : "f"(cc * df * df));
        df = mu - p0.z; asm("ex2.approx.ftz.f32 %0, %1;" : "=f"(e1) : "f"(cc * df * df));
        df = mu - p0.w; asm("ex2.approx.ftz.f32 %0, %1;" : "=f"(e2) : "f"(cc * df * df));
        df = mu - p1.x; asm("ex2.approx.ftz.f32 %0, %1;" : "=f"(e3) : "f"(cc * df * df));
        df = mu - p1.y; asm("ex2.approx.ftz.f32 %0, %1;" : "=f"(e4) : "f"(cc * df * df));

        // mean: sqrt(l2/d) * (e . alpha)
        float mdot = e0 * p1.z + e1 * p1.w + e2 * p2.x + e3 * p2.y + e4 * p2.z;
        float rs;
        asm("rsqrt.approx.ftz.f32 %0, %1;" : "=f"(rs) : "f"(l2d));
        accm += (l2d * rs) * mdot;            // l2d * rsqrt(l2d) = sqrt(l2d)

        // var: (l2/d) * || Linv e ||^2
        float w0 = p2.w * e0;
        float w1 = p3.x * e0 + p3.y * e1;
        float w2 = p3.z * e0 + p3.w * e1 + p4.x * e2;
        float w3 = p4.y * e0 + p4.z * e1 + p4.w * e2 + p5.x * e3;
        float w4 = p5.y * e0 + p5.z * e1 + p5.w * e2 + p6.x * e3 + p6.y * e4;
        float vdot = w0 * w0 + w1 * w1 + w2 * w2 + w3 * w3 + w4 * w4;
        accv += l2d * vdot;
    }

    const int row = row_base + r;
    out[row * OC + o] = accm;                                   // mean block
    out[NROWS * OC + row * OC + o] = fmaxf(72.0f - accv, 1e-6f); // var block
}

// ---------------------------------------------------------------------------
extern "C" void kernel_launch(void* const* d_in, const int* in_sizes, int n_in,
                              void* d_out, int out_size)
{
    const float* xm    = (const float*)d_in[0];  // x_mean [8,32,32,8]
    const float* xv    = (const float*)d_in[1];  // x_var  [8,32,32,8]
    const float* z     = (const float*)d_in[2];  // [16,72,5]
    const float* h     = (const float*)d_in[3];  // [16,72,5]
    const float* raw_l = (const float*)d_in[4];  // [16,72]
    float* out = (float*)d_out;                  // [mean(131072), var(131072)]

    gp_precompute<<<(OC * IDIM + 255) / 256, 256>>>(z, h, raw_l);
    gp_main<<<NROWS / 16, 256>>>(xm, xv, out);
}

// round 2
// speedup vs baseline: 1.6290x; 1.6290x over previous
#include <cuda_runtime.h>

// Problem constants
#define IHW   32
#define IC    8
#define OC    16
#define PP    5
#define IDIM  72            // IC*3*3
#define NROWS 8192          // N*OH*OW = 8*32*32
#define PSTRIDE 28          // params per (i,o), padded to 7 float4

// Precomputed per-(i,o) parameters, laid out [i][o][28]:
//  [0]=l2, [1..5]=z, [6..10]=alpha, [11..25]=Linv (lower tri row-major),
//  [26]=sqrt(l2), [27]=pad
__device__ float g_params[IDIM * OC * PSTRIDE];

// fp64 reciprocal-sqrt without divisions: float MUFU seed + 2 Newton iters
__device__ __forceinline__ double drsqrt(double x)
{
    float xf = (float)x, yf;
    asm("rsqrt.approx.ftz.f32 %0, %1;" : "=f"(yf) : "f"(xf));
    double y = (double)yf;
    y = y * (1.5 - 0.5 * x * y * y);
    y = y * (1.5 - 0.5 * x * y * y);
    return y;
}

// ---------------------------------------------------------------------------
// Kernel 1: per-neuron precompute (fp64; symmetry -> 10 exps; no divisions)
// ---------------------------------------------------------------------------
__global__ void gp_precompute(const float* __restrict__ z,
                              const float* __restrict__ h,
                              const float* __restrict__ raw_l)
{
    int idx = blockIdx.x * blockDim.x + threadIdx.x;
    if (idx >= OC * IDIM) return;
    int o = idx / IDIM;
    int i = idx % IDIM;

    double zz[PP], hh[PP];
#pragma unroll
    for (int p = 0; p < PP; p++) {
        zz[p] = (double)z[(o * IDIM + i) * PP + p];
        hh[p] = (double)h[(o * IDIM + i) * PP + p];
    }
    double rl = (double)raw_l[o * IDIM + i];
    double l  = log1p(exp(rl));        // softplus
    double l2 = l * l;
    double inv_l2 = drsqrt(l2); inv_l2 *= inv_l2;   // 1/l2, no division

    // K = exp(-0.5 dz^2 / l2) + 1e-4 I   (symmetric: 10 unique exps)
    double K[PP][PP];
#pragma unroll
    for (int a = 0; a < PP; a++) K[a][a] = 1.0 + 1e-4;
#pragma unroll
    for (int a = 0; a < PP; a++)
#pragma unroll
        for (int b = a + 1; b < PP; b++) {
            double d = zz[a] - zz[b];
            double e = exp(-0.5 * d * d * inv_l2);
            K[a][b] = e;
            K[b][a] = e;
        }

    // Cholesky: K = L L^T, keeping invdiag (no divisions)
    double L[PP][PP], invd[PP];
#pragma unroll
    for (int a = 0; a < PP; a++) {
        double s = K[a][a];
        for (int k = 0; k < a; k++) s -= L[a][k] * L[a][k];
        double rs = drsqrt(s);
        L[a][a] = s * rs;
        invd[a]  = rs;
        for (int b = a + 1; b < PP; b++) {
            double t = K[b][a];
            for (int k = 0; k < a; k++) t -= L[b][k] * L[a][k];
            L[b][a] = t * rs;
        }
    }

    // Linv (lower triangular inverse of L)
    double Li[PP][PP];
#pragma unroll
    for (int c = 0; c < PP; c++) {
        for (int a = 0; a < PP; a++) {
            if (a < c) { Li[a][c] = 0.0; continue; }
            double t = (a == c) ? 1.0 : 0.0;
            for (int k = c; k < a; k++) t -= L[a][k] * Li[k][c];
            Li[a][c] = t * invd[a];
        }
    }

    // alpha = K^{-1} h via two triangular solves
    double t1[PP];
#pragma unroll
    for (int a = 0; a < PP; a++) {
        double t = hh[a];
        for (int k = 0; k < a; k++) t -= L[a][k] * t1[k];
        t1[a] = t * invd[a];
    }
    double alpha[PP];
    for (int a = PP - 1; a >= 0; a--) {
        double t = t1[a];
        for (int k = a + 1; k < PP; k++) t -= L[k][a] * alpha[k];
        alpha[a] = t * invd[a];
    }

    float* pp = &g_params[(i * OC + o) * PSTRIDE];
    pp[0] = (float)l2;
#pragma unroll
    for (int p = 0; p < PP; p++) pp[1 + p] = (float)zz[p];
#pragma unroll
    for (int p = 0; p < PP; p++) pp[6 + p] = (float)alpha[p];
    int k = 11;
#pragma unroll
    for (int a = 0; a < PP; a++)
#pragma unroll
        for (int b = 0; b <= a; b++) pp[k++] = (float)Li[a][b];
    pp[26] = (float)l;   // sqrt(l2)
    pp[27] = 0.0f;
}

// ---------------------------------------------------------------------------
// Kernel 2: main GP moment propagation.
// CTA = 512 threads = 16 warps. Warp w handles output channel o=w for the
// CTA's 32 pixels; lane = pixel. Param loads are warp-uniform (1 L1 wavefront).
// ---------------------------------------------------------------------------
__global__ __launch_bounds__(512) void gp_main(const float* __restrict__ xm,
                                               const float* __restrict__ xv,
                                               float* __restrict__ out)
{
    __shared__ float mu_s[IDIM * 32];
    __shared__ float s2_s[IDIM * 32];

    const int tid = threadIdx.x;
    const int row_base = blockIdx.x * 32;   // 32 pixels = one full ow row

    // ---- stage im2col patch means/vars for the 32 pixels into smem ----
    {
        const int n  = row_base >> 10;
        const int oh = (row_base >> 5) & 31;
        for (int idx = tid; idx < IDIM * 32; idx += 512) {
            int r  = idx & 31;
            int i  = idx >> 5;
            int c  = i / 9;
            int k9 = i - c * 9;
            int kh = k9 / 3;
            int kw = k9 - kh * 3;
            int y  = oh + kh - 1;
            int x  = r + kw - 1;
            float m = 0.0f, v = 0.0f;
            if ((unsigned)y < 32u && (unsigned)x < 32u) {
                int g = ((n * IHW + y) * IHW + x) * IC + c;
                m = xm[g];
                v = xv[g];
            }
            mu_s[i * 32 + r] = m;
            s2_s[i * 32 + r] = v;
        }
    }
    __syncthreads();

    const int o    = tid >> 5;    // warp-uniform output channel
    const int lane = tid & 31;    // pixel within the block
    const float4* __restrict__ pbase = (const float4*)g_params;

    float accm = 0.0f;
    float accv = 0.0f;

#pragma unroll 2
    for (int i = 0; i < IDIM; i++) {
        const float mu = mu_s[i * 32 + lane];
        const float s2 = s2_s[i * 32 + lane];

        const float4* pp = pbase + (i * OC + o) * 7;   // warp-uniform address
        float4 p0 = pp[0];   // l2, z0, z1, z2
        float4 p1 = pp[1];   // z3, z4, a0, a1
        float4 p2 = pp[2];   // a2, a3, a4, L00
        float4 p3 = pp[3];   // L10, L11, L20, L21
        float4 p4 = pp[4];   // L22, L30, L31, L32
        float4 p5 = pp[5];   // L33, L40, L41, L42
        float4 p6 = pp[6];   // L43, L44, sqrt(l2), pad

        float l2 = p0.x;
        float d  = l2 + s2;
        float rs;
        asm("rsqrt.approx.ftz.f32 %0, %1;" : "=f"(rs) : "f"(d));
        float inv_d = rs * rs;
        float cc  = -0.7213475204f * inv_d;   // -0.5 * log2(e) / d
        float l2d = l2 * inv_d;               // l2/d (no sqrt in var path)

        float df, e0, e1, e2, e3, e4;
        df = mu - p0.y; asm("ex2.approx.ftz.f32 %0, %1;" : "=f"(e0) : "f"(cc * df * df));
        df = mu - p0.z; asm("ex2.approx.ftz.f32 %0, %1;" : "=f"(e1) : "f"(cc * df * df));
        df = mu - p0.w; asm("ex2.approx.ftz.f32 %0, %1;" : "=f"(e2) : "f"(cc * df * df));
        df = mu - p1.x; asm("ex2.approx.ftz.f32 %0, %1;" : "=f"(e3) : "f"(cc * df * df));
        df = mu - p1.y; asm("ex2.approx.ftz.f32 %0, %1;" : "=f"(e4) : "f"(cc * df * df));

        // mean: sqrt(l2)/sqrt(d) * (e . alpha)
        float mdot = e0 * p1.z + e1 * p1.w + e2 * p2.x + e3 * p2.y + e4 * p2.z;
        accm = fmaf(p6.z * rs, mdot, accm);   // sqrt(l2) * rsqrt(d)

        // var: (l2/d) * || Linv e ||^2
        float w0 = p2.w * e0;
        float w1 = p3.x * e0 + p3.y * e1;
        float w2 = p3.z * e0 + p3.w * e1 + p4.x * e2;
        float w3 = p4.y * e0 + p4.z * e1 + p4.w * e2 + p5.x * e3;
        float w4 = p5.y * e0 + p5.z * e1 + p5.w * e2 + p6.x * e3 + p6.y * e4;
        float vdot = w0 * w0 + w1 * w1 + w2 * w2 + w3 * w3 + w4 * w4;
        accv = fmaf(l2d, vdot, accv);
    }

    const int row = row_base + lane;
    out[row * OC + o] = accm;                                    // mean block
    out[NROWS * OC + row * OC + o] = fmaxf(72.0f - accv, 1e-6f); // var block
}

// ---------------------------------------------------------------------------
extern "C" void kernel_launch(void* const* d_in, const int* in_sizes, int n_in,
                              void* d_out, int out_size)
{
    const float* xm    = (const float*)d_in[0];  // x_mean [8,32,32,8]
    const float* xv    = (const float*)d_in[1];  // x_var  [8,32,32,8]
    const float* z     = (const float*)d_in[2];  // [16,72,5]
    const float* h     = (const float*)d_in[3];  // [16,72,5]
    const float* raw_l = (const float*)d_in[4];  // [16,72]
    float* out = (float*)d_out;                  // [mean(131072), var(131072)]

    gp_precompute<<<(OC * IDIM + 255) / 256, 256>>>(z, h, raw_l);
    gp_main<<<NROWS / 32, 512>>>(xm, xv, out);
}

// round 3
// speedup vs baseline: 2.0473x; 1.2568x over previous
#include <cuda_runtime.h>

typedef unsigned long long u64;

// Problem constants
#define IHW   32
#define IC    8
#define OC    16
#define PP    5
#define IDIM  72            // IC*3*3
#define NROWS 8192          // N*OH*OW = 8*32*32
#define RECF  56            // floats per (i,o) record (27 packed pairs + pad)

// Precomputed per-(i,o) params, duplicated pairs for f32x2 consumption.
// u64-pair order: l2, -z0..-z4, a0..a4, L00,L10,L11,L20,L21,L22,L30,L31,L32,
//                 L33,L40,L41,L42,L43,L44, sqrt(l2), pad
__device__ float g_params[IDIM * OC * RECF];

// ---------------------------------------------------------------------------
// f32x2 helpers (sm_103a packed fp32)
// ---------------------------------------------------------------------------
__device__ __forceinline__ u64 pk2(float a, float b) {
    u64 r; asm("mov.b64 %0, {%1, %2};" : "=l"(r) : "f"(a), "f"(b)); return r;
}
__device__ __forceinline__ void upk2(u64 v, float& a, float& b) {
    asm("mov.b64 {%0, %1}, %2;" : "=f"(a), "=f"(b) : "l"(v));
}
__device__ __forceinline__ u64 fma2(u64 a, u64 b, u64 c) {
    u64 r; asm("fma.rn.f32x2 %0, %1, %2, %3;" : "=l"(r) : "l"(a), "l"(b), "l"(c)); return r;
}
__device__ __forceinline__ u64 mul2(u64 a, u64 b) {
    u64 r; asm("mul.rn.f32x2 %0, %1, %2;" : "=l"(r) : "l"(a), "l"(b)); return r;
}
__device__ __forceinline__ u64 add2(u64 a, u64 b) {
    u64 r; asm("add.rn.f32x2 %0, %1, %2;" : "=l"(r) : "l"(a), "l"(b)); return r;
}
__device__ __forceinline__ u64 ex2_2(u64 v) {
    float a, b; upk2(v, a, b);
    asm("ex2.approx.ftz.f32 %0, %0;" : "+f"(a));
    asm("ex2.approx.ftz.f32 %0, %0;" : "+f"(b));
    return pk2(a, b);
}
__device__ __forceinline__ u64 rsqrt_2(u64 v) {
    float a, b; upk2(v, a, b);
    asm("rsqrt.approx.ftz.f32 %0, %0;" : "+f"(a));
    asm("rsqrt.approx.ftz.f32 %0, %0;" : "+f"(b));
    return pk2(a, b);
}

// fp64 reciprocal-sqrt without divisions: float MUFU seed + 2 Newton iters
__device__ __forceinline__ double drsqrt(double x)
{
    float xf = (float)x, yf;
    asm("rsqrt.approx.ftz.f32 %0, %1;" : "=f"(yf) : "f"(xf));
    double y = (double)yf;
    y = y * (1.5 - 0.5 * x * y * y);
    y = y * (1.5 - 0.5 * x * y * y);
    return y;
}

// ---------------------------------------------------------------------------
// Kernel 1: per-neuron precompute.
// fp32 for softplus + K-matrix exps (matches the fp32 reference's K);
// fp64 only for the 5x5 Cholesky / triangular solves (cheap, well-pipelined).
// ---------------------------------------------------------------------------
__global__ void gp_precompute(const float* __restrict__ z,
                              const float* __restrict__ h,
                              const float* __restrict__ raw_l)
{
    int idx = blockIdx.x * blockDim.x + threadIdx.x;
    if (idx >= OC * IDIM) return;
    int o = idx / IDIM;
    int i = idx % IDIM;

    float zf[PP];
    double hh[PP];
#pragma unroll
    for (int p = 0; p < PP; p++) {
        zf[p] = z[(o * IDIM + i) * PP + p];
        hh[p] = (double)h[(o * IDIM + i) * PP + p];
    }
    float rl  = raw_l[o * IDIM + i];
    float lf  = log1pf(expf(rl));        // softplus (fp32, well-conditioned)
    float l2f = lf * lf;
    float inv_l2f = 1.0f / l2f;

    // K = exp(-0.5 dz^2 / l2) + 1e-4 I   (fp32 entries, like the reference)
    double K[PP][PP];
#pragma unroll
    for (int a = 0; a < PP; a++) K[a][a] = 1.0 + 1e-4;
#pragma unroll
    for (int a = 0; a < PP; a++)
#pragma unroll
        for (int b = a + 1; b < PP; b++) {
            float d = zf[a] - zf[b];
            double e = (double)expf(-0.5f * d * d * inv_l2f);
            K[a][b] = e;
            K[b][a] = e;
        }

    // fp64 Cholesky: K = L L^T, keeping invdiag (no divisions)
    double L[PP][PP], invd[PP];
#pragma unroll
    for (int a = 0; a < PP; a++) {
        double s = K[a][a];
        for (int k = 0; k < a; k++) s -= L[a][k] * L[a][k];
        double rs = drsqrt(s);
        L[a][a] = s * rs;
        invd[a] = rs;
        for (int b = a + 1; b < PP; b++) {
            double t = K[b][a];
            for (int k = 0; k < a; k++) t -= L[b][k] * L[a][k];
            L[b][a] = t * rs;
        }
    }

    // Linv (lower triangular inverse of L)
    double Li[PP][PP];
#pragma unroll
    for (int c = 0; c < PP; c++) {
        for (int a = 0; a < PP; a++) {
            if (a < c) { Li[a][c] = 0.0; continue; }
            double t = (a == c) ? 1.0 : 0.0;
            for (int k = c; k < a; k++) t -= L[a][k] * Li[k][c];
            Li[a][c] = t * invd[a];
        }
    }

    // alpha = K^{-1} h via two triangular solves
    double t1[PP];
#pragma unroll
    for (int a = 0; a < PP; a++) {
        double t = hh[a];
        for (int k = 0; k < a; k++) t -= L[a][k] * t1[k];
        t1[a] = t * invd[a];
    }
    double alpha[PP];
    for (int a = PP - 1; a >= 0; a--) {
        double t = t1[a];
        for (int k = a + 1; k < PP; k++) t -= L[k][a] * alpha[k];
        alpha[a] = t * invd[a];
    }

    // Emit duplicated-pair record
    float vals[28];
    vals[0] = l2f;
#pragma unroll
    for (int p = 0; p < PP; p++) vals[1 + p] = -zf[p];
#pragma unroll
    for (int p = 0; p < PP; p++) vals[6 + p] = (float)alpha[p];
    int k = 11;
#pragma unroll
    for (int a = 0; a < PP; a++)
#pragma unroll
        for (int b = 0; b <= a; b++) vals[k++] = (float)Li[a][b];
    vals[26] = lf;       // sqrt(l2)
    vals[27] = 0.0f;

    float* pp = &g_params[(i * OC + o) * RECF];
#pragma unroll
    for (int j = 0; j < 28; j++) { pp[2 * j] = vals[j]; pp[2 * j + 1] = vals[j]; }
}

// ---------------------------------------------------------------------------
// Kernel 2: main GP moment propagation, packed f32x2.
// CTA = 128 threads = 4 warps = 4 output channels x 64 pixels (2 ow-rows).
// Each thread: lane-th pixel of rows oh0 and oh0+1, packed in one f32x2 lane.
// Params are warp-uniform LDG.128 of pre-duplicated pairs.
// Input staged as raw halo tile [4 rows][34 x][9-padded c] -> conflict-free LDS.
// ---------------------------------------------------------------------------
#define TROW 306           // 34 * 9 words per tile row
__global__ __launch_bounds__(128) void gp_main(const float* __restrict__ xm,
                                               const float* __restrict__ xv,
                                               float* __restrict__ out)
{
    __shared__ float raw_m[4 * TROW];
    __shared__ float raw_v[4 * TROW];

    const int tid  = threadIdx.x;
    const int warp = tid >> 5;
    const int lane = tid & 31;

    const int g    = blockIdx.x >> 2;          // 128 pixel groups of 64
    const int o    = ((blockIdx.x & 3) << 2) + warp;
    const int base = g * 64;
    const int n    = base >> 10;
    const int oh0  = (base >> 5) & 31;         // even

    // ---- zero halo + fill interior rows (coalesced gmem reads) ----
    for (int j = tid; j < 4 * TROW; j += 128) { raw_m[j] = 0.0f; raw_v[j] = 0.0f; }
    __syncthreads();
    for (int j = tid; j < 4 * 256; j += 128) {
        int t = j >> 8;                // tile row 0..3  -> y = oh0-1+t
        int r = j & 255;
        int x = r >> 3;
        int c = r & 7;
        int y = oh0 - 1 + t;
        if ((unsigned)y < 32u) {
            int gidx = ((n * IHW + y) * IHW + x) * IC + c;
            int sidx = t * TROW + (x + 1) * 9 + c;
            raw_m[sidx] = xm[gidx];
            raw_v[sidx] = xv[gidx];
        }
    }
    __syncthreads();

    const ulonglong2* __restrict__ pbase =
        (const ulonglong2*)g_params + (size_t)o * 14;   // record = 14 ulonglong2

    const u64 kneg = pk2(-0.7213475204f, -0.7213475204f);  // -0.5*log2(e)
    u64 accm = 0ull;   // (0.0f, 0.0f)
    u64 accv = 0ull;

#pragma unroll 1
    for (int c = 0; c < IC; c++) {
        const float* bm = raw_m + lane * 9 + c;
        const float* bv = raw_v + lane * 9 + c;
#pragma unroll
        for (int k9 = 0; k9 < 9; k9++) {
            const int kh = k9 / 3;
            const int kw = k9 % 3;
            const int i  = c * 9 + k9;

            const ulonglong2* pp = pbase + (size_t)i * (OC * 14);
            ulonglong2 v0 = pp[0],  v1 = pp[1],  v2 = pp[2],  v3 = pp[3];
            ulonglong2 v4 = pp[4],  v5 = pp[5],  v6 = pp[6];
            ulonglong2 v7 = pp[7],  v8 = pp[8],  v9 = pp[9],  v10 = pp[10];
            ulonglong2 v11 = pp[11], v12 = pp[12], v13 = pp[13];

            const int off = kh * TROW + kw * 9;
            u64 mu2 = pk2(bm[off], bm[off + TROW]);
            u64 s22 = pk2(bv[off], bv[off + TROW]);

            u64 d2    = add2(v0.x, s22);          // l2 + s2
            u64 rs2   = rsqrt_2(d2);
            u64 invd2 = mul2(rs2, rs2);
            u64 cc2   = mul2(kneg, invd2);
            u64 l2d2  = mul2(v0.x, invd2);        // l2/d

            u64 e0, e1, e2, e3, e4, df;
            df = add2(mu2, v0.y); e0 = ex2_2(mul2(mul2(df, df), cc2));
            df = add2(mu2, v1.x); e1 = ex2_2(mul2(mul2(df, df), cc2));
            df = add2(mu2, v1.y); e2 = ex2_2(mul2(mul2(df, df), cc2));
            df = add2(mu2, v2.x); e3 = ex2_2(mul2(mul2(df, df), cc2));
            df = add2(mu2, v2.y); e4 = ex2_2(mul2(mul2(df, df), cc2));

            // mean: sqrt(l2)*rsqrt(d) * (e . alpha)
            u64 md = mul2(e0, v3.x);
            md = fma2(e1, v3.y, md);
            md = fma2(e2, v4.x, md);
            md = fma2(e3, v4.y, md);
            md = fma2(e4, v5.x, md);
            accm = fma2(mul2(v13.x, rs2), md, accm);

            // var: (l2/d) * || Linv e ||^2
            u64 w0 = mul2(v5.y, e0);
            u64 w1 = fma2(v6.y, e1, mul2(v6.x, e0));
            u64 w2 = fma2(v8.x, e2, fma2(v7.y, e1, mul2(v7.x, e0)));
            u64 w3 = fma2(v10.x, e3, fma2(v9.y, e2, fma2(v9.x, e1, mul2(v8.y, e0))));
            u64 w4 = fma2(v12.y, e4, fma2(v12.x, e3,
                     fma2(v11.y, e2, fma2(v11.x, e1, mul2(v10.y, e0)))));
            u64 vd = mul2(w0, w0);
            vd = fma2(w1, w1, vd);
            vd = fma2(w2, w2, vd);
            vd = fma2(w3, w3, vd);
            vd = fma2(w4, w4, vd);
            accv = fma2(l2d2, vd, accv);
        }
    }

    float mA, mB, vA, vB;
    upk2(accm, mA, mB);
    upk2(accv, vA, vB);
    const int rowA = base + lane;          // (n, oh0,   lane)
    const int rowB = base + 32 + lane;     // (n, oh0+1, lane)
    out[rowA * OC + o] = mA;
    out[rowB * OC + o] = mB;
    out[NROWS * OC + rowA * OC + o] = fmaxf(72.0f - vA, 1e-6f);
    out[NROWS * OC + rowB * OC + o] = fmaxf(72.0f - vB, 1e-6f);
}

// ---------------------------------------------------------------------------
extern "C" void kernel_launch(void* const* d_in, const int* in_sizes, int n_in,
                              void* d_out, int out_size)
{
    const float* xm    = (const float*)d_in[0];  // x_mean [8,32,32,8]
    const float* xv    = (const float*)d_in[1];  // x_var  [8,32,32,8]
    const float* z     = (const float*)d_in[2];  // [16,72,5]
    const float* h     = (const float*)d_in[3];  // [16,72,5]
    const float* raw_l = (const float*)d_in[4];  // [16,72]
    float* out = (float*)d_out;                  // [mean(131072), var(131072)]

    gp_precompute<<<(OC * IDIM + 127) / 128, 128>>>(z, h, raw_l);
    gp_main<<<512, 128>>>(xm, xv, out);
}

// round 5
// speedup vs baseline: 2.5831x; 1.2617x over previous
#include <cuda_runtime.h>

typedef unsigned long long u64;

// Problem constants
#define IHW   32
#define IC    8
#define OC    16
#define PP    5
#define IDIM  72            // IC*3*3
#define NROWS 8192          // N*OH*OW = 8*32*32
#define RECF  52            // floats per (i,o) record: 26 duplicated pairs
#define RECQ  13            // ulonglong2 per record

// Precomputed per-(i,o) params, duplicated pairs for f32x2 consumption.
// pair order: l2, -z0..-z4, a'0..a'4 (= sqrt(l2)*alpha),
//             L'00..L'44 (= sqrt(l2)*Linv lower tri row-major, 15 vals)
__device__ float g_params[IDIM * OC * RECF];

// ---------------------------------------------------------------------------
// f32x2 helpers (sm_103a packed fp32)
// ---------------------------------------------------------------------------
__device__ __forceinline__ u64 pk2(float a, float b) {
    u64 r; asm("mov.b64 %0, {%1, %2};" : "=l"(r) : "f"(a), "f"(b)); return r;
}
__device__ __forceinline__ void upk2(u64 v, float& a, float& b) {
    asm("mov.b64 {%0, %1}, %2;" : "=f"(a), "=f"(b) : "l"(v));
}
__device__ __forceinline__ u64 fma2(u64 a, u64 b, u64 c) {
    u64 r; asm("fma.rn.f32x2 %0, %1, %2, %3;" : "=l"(r) : "l"(a), "l"(b), "l"(c)); return r;
}
__device__ __forceinline__ u64 mul2(u64 a, u64 b) {
    u64 r; asm("mul.rn.f32x2 %0, %1, %2;" : "=l"(r) : "l"(a), "l"(b)); return r;
}
__device__ __forceinline__ u64 add2(u64 a, u64 b) {
    u64 r; asm("add.rn.f32x2 %0, %1, %2;" : "=l"(r) : "l"(a), "l"(b)); return r;
}
__device__ __forceinline__ u64 ex2_2(u64 v) {
    float a, b; upk2(v, a, b);
    asm("ex2.approx.ftz.f32 %0, %0;" : "+f"(a));
    asm("ex2.approx.ftz.f32 %0, %0;" : "+f"(b));
    return pk2(a, b);
}
__device__ __forceinline__ u64 rsqrt_2(u64 v) {
    float a, b; upk2(v, a, b);
    asm("rsqrt.approx.ftz.f32 %0, %0;" : "+f"(a));
    asm("rsqrt.approx.ftz.f32 %0, %0;" : "+f"(b));
    return pk2(a, b);
}

// fp64 reciprocal-sqrt without divisions: float MUFU seed + 2 Newton iters
__device__ __forceinline__ double drsqrt(double x)
{
    float xf = (float)x, yf;
    asm("rsqrt.approx.ftz.f32 %0, %1;" : "=f"(yf) : "f"(xf));
    double y = (double)yf;
    y = y * (1.5 - 0.5 * x * y * y);
    y = y * (1.5 - 0.5 * x * y * y);
    return y;
}

// ---------------------------------------------------------------------------
// Kernel 1: per-neuron precompute.
// fp32 softplus + K-matrix exps (matches fp32 reference K); fp64 5x5 solves.
// ---------------------------------------------------------------------------
__global__ void gp_precompute(const float* __restrict__ z,
                              const float* __restrict__ h,
                              const float* __restrict__ raw_l)
{
    int idx = blockIdx.x * blockDim.x + threadIdx.x;
    if (idx >= OC * IDIM) return;
    int o = idx / IDIM;
    int i = idx % IDIM;

    float zf[PP];
    double hh[PP];
#pragma unroll
    for (int p = 0; p < PP; p++) {
        zf[p] = z[(o * IDIM + i) * PP + p];
        hh[p] = (double)h[(o * IDIM + i) * PP + p];
    }
    float rl  = raw_l[o * IDIM + i];
    float lf  = log1pf(expf(rl));        // softplus
    float l2f = lf * lf;
    float inv_l2f = 1.0f / l2f;

    // K = exp(-0.5 dz^2 / l2) + 1e-4 I   (fp32 entries, like the reference)
    double K[PP][PP];
#pragma unroll
    for (int a = 0; a < PP; a++) K[a][a] = 1.0 + 1e-4;
#pragma unroll
    for (int a = 0; a < PP; a++)
#pragma unroll
        for (int b = a + 1; b < PP; b++) {
            float d = zf[a] - zf[b];
            double e = (double)expf(-0.5f * d * d * inv_l2f);
            K[a][b] = e;
            K[b][a] = e;
        }

    // fp64 Cholesky: K = L L^T, keeping invdiag (no divisions)
    double L[PP][PP], invd[PP];
#pragma unroll
    for (int a = 0; a < PP; a++) {
        double s = K[a][a];
        for (int k = 0; k < a; k++) s -= L[a][k] * L[a][k];
        double rs = drsqrt(s);
        L[a][a] = s * rs;
        invd[a] = rs;
        for (int b = a + 1; b < PP; b++) {
            double t = K[b][a];
            for (int k = 0; k < a; k++) t -= L[b][k] * L[a][k];
            L[b][a] = t * rs;
        }
    }

    // Linv (lower triangular inverse of L)
    double Li[PP][PP];
#pragma unroll
    for (int c = 0; c < PP; c++) {
        for (int a = 0; a < PP; a++) {
            if (a < c) { Li[a][c] = 0.0; continue; }
            double t = (a == c) ? 1.0 : 0.0;
            for (int k = c; k < a; k++) t -= L[a][k] * Li[k][c];
            Li[a][c] = t * invd[a];
        }
    }

    // alpha = K^{-1} h via two triangular solves
    double t1[PP];
#pragma unroll
    for (int a = 0; a < PP; a++) {
        double t = hh[a];
        for (int k = 0; k < a; k++) t -= L[a][k] * t1[k];
        t1[a] = t * invd[a];
    }
    double alpha[PP];
    for (int a = PP - 1; a >= 0; a--) {
        double t = t1[a];
        for (int k = a + 1; k < PP; k++) t -= L[k][a] * alpha[k];
        alpha[a] = t * invd[a];
    }

    // Emit 26 duplicated pairs; sqrt(l2) folded into alpha and Linv.
    float vals[26];
    vals[0] = l2f;
#pragma unroll
    for (int p = 0; p < PP; p++) vals[1 + p] = -zf[p];
#pragma unroll
    for (int p = 0; p < PP; p++) vals[6 + p] = lf * (float)alpha[p];
    int k = 11;
#pragma unroll
    for (int a = 0; a < PP; a++)
#pragma unroll
        for (int b = 0; b <= a; b++) vals[k++] = lf * (float)Li[a][b];

    float* pp = &g_params[(i * OC + o) * RECF];
#pragma unroll
    for (int j = 0; j < 26; j++) { pp[2 * j] = vals[j]; pp[2 * j + 1] = vals[j]; }
}

// ---------------------------------------------------------------------------
// Kernel 2: main GP moment propagation, packed f32x2 + i-split for occupancy.
// CTA = 128 threads = 4 warps = 2 output channels x 2 input-channel halves,
// covering 64 pixels (2 ow-rows packed per thread lane).
// Grid = 128 pixel-groups x 8 channel-pairs = 1024 CTAs (~28 warps/SM).
// ---------------------------------------------------------------------------
#define TROW 306           // 34 * 9 words per tile row
__global__ __launch_bounds__(128) void gp_main(const float* __restrict__ xm,
                                               const float* __restrict__ xv,
                                               float* __restrict__ out)
{
    __shared__ float raw_m[4 * TROW];
    __shared__ float raw_v[4 * TROW];
    __shared__ u64 red_m[2][32];
    __shared__ u64 red_v[2][32];

    const int tid  = threadIdx.x;
    const int warp = tid >> 5;
    const int lane = tid & 31;

    const int g    = blockIdx.x >> 3;          // 128 pixel groups of 64
    const int op   = blockIdx.x & 7;           // channel pair
    const int o    = op * 2 + (warp >> 1);
    const int ih   = warp & 1;                 // input-channel half
    const int base = g * 64;
    const int n    = base >> 10;
    const int oh0  = (base >> 5) & 31;         // even

    // ---- zero halo + fill interior rows (coalesced gmem reads) ----
    for (int j = tid; j < 4 * TROW; j += 128) { raw_m[j] = 0.0f; raw_v[j] = 0.0f; }
    __syncthreads();
    for (int j = tid; j < 4 * 256; j += 128) {
        int t = j >> 8;                // tile row 0..3  -> y = oh0-1+t
        int r = j & 255;
        int x = r >> 3;
        int c = r & 7;
        int y = oh0 - 1 + t;
        if ((unsigned)y < 32u) {
            int gidx = ((n * IHW + y) * IHW + x) * IC + c;
            int sidx = t * TROW + (x + 1) * 9 + c;
            raw_m[sidx] = xm[gidx];
            raw_v[sidx] = xv[gidx];
        }
    }
    __syncthreads();

    const ulonglong2* __restrict__ pbase =
        (const ulonglong2*)g_params + (size_t)o * RECQ;

    const u64 kneg = pk2(-0.7213475204f, -0.7213475204f);  // -0.5*log2(e)
    u64 accm = 0ull;
    u64 accv = 0ull;

#pragma unroll 1
    for (int c = ih * 4; c < ih * 4 + 4; c++) {
        const float* bm = raw_m + lane * 9 + c;
        const float* bv = raw_v + lane * 9 + c;
#pragma unroll
        for (int k9 = 0; k9 < 9; k9++) {
            const int kh = k9 / 3;
            const int kw = k9 % 3;
            const int i  = c * 9 + k9;

            const ulonglong2* pp = pbase + (size_t)i * (OC * RECQ);
            ulonglong2 v0 = pp[0],  v1 = pp[1],  v2 = pp[2],  v3 = pp[3];
            ulonglong2 v4 = pp[4],  v5 = pp[5],  v6 = pp[6];
            ulonglong2 v7 = pp[7],  v8 = pp[8],  v9 = pp[9],  v10 = pp[10];
            ulonglong2 v11 = pp[11], v12 = pp[12];

            const int off = kh * TROW + kw * 9;
            u64 mu2 = pk2(bm[off], bm[off + TROW]);
            u64 s22 = pk2(bv[off], bv[off + TROW]);

            u64 d2    = add2(v0.x, s22);          // l2 + s2
            u64 rs2   = rsqrt_2(d2);              // 1/sqrt(d)
            u64 invd2 = mul2(rs2, rs2);           // 1/d
            u64 cc2   = mul2(kneg, invd2);

            u64 e0, e1, e2, e3, e4, df;
            df = add2(mu2, v0.y); e0 = ex2_2(mul2(mul2(df, df), cc2));
            df = add2(mu2, v1.x); e1 = ex2_2(mul2(mul2(df, df), cc2));
            df = add2(mu2, v1.y); e2 = ex2_2(mul2(mul2(df, df), cc2));
            df = add2(mu2, v2.x); e3 = ex2_2(mul2(mul2(df, df), cc2));
            df = add2(mu2, v2.y); e4 = ex2_2(mul2(mul2(df, df), cc2));

            // mean: rsqrt(d) * (e . alpha')      [alpha' = sqrt(l2)*alpha]
            u64 md = mul2(e0, v3.x);
            md = fma2(e1, v3.y, md);
            md = fma2(e2, v4.x, md);
            md = fma2(e3, v4.y, md);
            md = fma2(e4, v5.x, md);
            accm = fma2(rs2, md, accm);

            // var: (1/d) * || L' e ||^2          [L' = sqrt(l2)*Linv]
            u64 w0 = mul2(v5.y, e0);
            u64 w1 = fma2(v6.y, e1, mul2(v6.x, e0));
            u64 w2 = fma2(v8.x, e2, fma2(v7.y, e1, mul2(v7.x, e0)));
            u64 w3 = fma2(v10.x, e3, fma2(v9.y, e2, fma2(v9.x, e1, mul2(v8.y, e0))));
            u64 w4 = fma2(v12.y, e4, fma2(v12.x, e3,
                     fma2(v11.y, e2, fma2(v11.x, e1, mul2(v10.y, e0)))));
            u64 vd = mul2(w0, w0);
            vd = fma2(w1, w1, vd);
            vd = fma2(w2, w2, vd);
            vd = fma2(w3, w3, vd);
            vd = fma2(w4, w4, vd);
            accv = fma2(invd2, vd, accv);
        }
    }

    // ---- pair-reduce the two i-halves, then write (ih==0 warps) ----
    if (ih) {
        red_m[warp >> 1][lane] = accm;
        red_v[warp >> 1][lane] = accv;
    }
    __syncthreads();
    if (!ih) {
        accm = add2(accm, red_m[warp >> 1][lane]);
        accv = add2(accv, red_v[warp >> 1][lane]);
        float mA, mB, vA, vB;
        upk2(accm, mA, mB);
        upk2(accv, vA, vB);
        const int rowA = base + lane;          // (n, oh0,   lane)
        const int rowB = base + 32 + lane;     // (n, oh0+1, lane)
        out[rowA * OC + o] = mA;
        out[rowB * OC + o] = mB;
        out[NROWS * OC + rowA * OC + o] = fmaxf(72.0f - vA, 1e-6f);
        out[NROWS * OC + rowB * OC + o] = fmaxf(72.0f - vB, 1e-6f);
    }
}

// ---------------------------------------------------------------------------
extern "C" void kernel_launch(void* const* d_in, const int* in_sizes, int n_in,
                              void* d_out, int out_size)
{
    const float* xm    = (const float*)d_in[0];  // x_mean [8,32,32,8]
    const float* xv    = (const float*)d_in[1];  // x_var  [8,32,32,8]
    const float* z     = (const float*)d_in[2];  // [16,72,5]
    const float* h     = (const float*)d_in[3];  // [16,72,5]
    const float* raw_l = (const float*)d_in[4];  // [16,72]
    float* out = (float*)d_out;                  // [mean(131072), var(131072)]

    gp_precompute<<<(OC * IDIM + 127) / 128, 128>>>(z, h, raw_l);
    gp_main<<<1024, 128>>>(xm, xv, out);
}

// round 6
// speedup vs baseline: 3.2315x; 1.2510x over previous
#include <cuda_runtime.h>

typedef unsigned long long u64;

// Problem constants
#define IHW   32
#define IC    8
#define OC    16
#define PP    5
#define IDIM  72            // IC*3*3
#define NROWS 8192          // N*OH*OW = 8*32*32
#define RECF  52            // floats per (i,o) record: 26 duplicated pairs
#define RECQ  13            // ulonglong2 per record

// Precomputed per-(i,o) params, duplicated pairs for f32x2 consumption.
// pair order: l2, -z0..-z4, a'0..a'4 (= sqrt(l2)*alpha),
//             L'00..L'44 (= sqrt(l2)*Linv lower tri row-major, 15 vals)
__device__ float g_params[IDIM * OC * RECF];

// ---------------------------------------------------------------------------
// f32x2 helpers (sm_103a packed fp32)
// ---------------------------------------------------------------------------
__device__ __forceinline__ u64 pk2(float a, float b) {
    u64 r; asm("mov.b64 %0, {%1, %2};" : "=l"(r) : "f"(a), "f"(b)); return r;
}
__device__ __forceinline__ void upk2(u64 v, float& a, float& b) {
    asm("mov.b64 {%0, %1}, %2;" : "=f"(a), "=f"(b) : "l"(v));
}
__device__ __forceinline__ u64 fma2(u64 a, u64 b, u64 c) {
    u64 r; asm("fma.rn.f32x2 %0, %1, %2, %3;" : "=l"(r) : "l"(a), "l"(b), "l"(c)); return r;
}
__device__ __forceinline__ u64 mul2(u64 a, u64 b) {
    u64 r; asm("mul.rn.f32x2 %0, %1, %2;" : "=l"(r) : "l"(a), "l"(b)); return r;
}
__device__ __forceinline__ u64 add2(u64 a, u64 b) {
    u64 r; asm("add.rn.f32x2 %0, %1, %2;" : "=l"(r) : "l"(a), "l"(b)); return r;
}
__device__ __forceinline__ u64 ex2_2(u64 v) {
    float a, b; upk2(v, a, b);
    asm("ex2.approx.ftz.f32 %0, %0;" : "+f"(a));
    asm("ex2.approx.ftz.f32 %0, %0;" : "+f"(b));
    return pk2(a, b);
}
__device__ __forceinline__ u64 rsqrt_2(u64 v) {
    float a, b; upk2(v, a, b);
    asm("rsqrt.approx.ftz.f32 %0, %0;" : "+f"(a));
    asm("rsqrt.approx.ftz.f32 %0, %0;" : "+f"(b));
    return pk2(a, b);
}

// fp64 reciprocal-sqrt without divisions: float MUFU seed + 2 Newton iters
__device__ __forceinline__ double drsqrt(double x)
{
    float xf = (float)x, yf;
    asm("rsqrt.approx.ftz.f32 %0, %1;" : "=f"(yf) : "f"(xf));
    double y = (double)yf;
    y = y * (1.5 - 0.5 * x * y * y);
    y = y * (1.5 - 0.5 * x * y * y);
    return y;
}

// ---------------------------------------------------------------------------
// Kernel 1: per-neuron precompute.
// fp32 softplus + K-matrix exps (matches fp32 reference K); fp64 5x5 solves.
// ---------------------------------------------------------------------------
__global__ void gp_precompute(const float* __restrict__ z,
                              const float* __restrict__ h,
                              const float* __restrict__ raw_l)
{
    int idx = blockIdx.x * blockDim.x + threadIdx.x;
    if (idx >= OC * IDIM) return;
    int o = idx / IDIM;
    int i = idx % IDIM;

    float zf[PP];
    double hh[PP];
#pragma unroll
    for (int p = 0; p < PP; p++) {
        zf[p] = z[(o * IDIM + i) * PP + p];
        hh[p] = (double)h[(o * IDIM + i) * PP + p];
    }
    float rl  = raw_l[o * IDIM + i];
    float lf  = log1pf(expf(rl));        // softplus
    float l2f = lf * lf;
    float inv_l2f = 1.0f / l2f;

    // K = exp(-0.5 dz^2 / l2) + 1e-4 I   (fp32 entries, like the reference)
    double K[PP][PP];
#pragma unroll
    for (int a = 0; a < PP; a++) K[a][a] = 1.0 + 1e-4;
#pragma unroll
    for (int a = 0; a < PP; a++)
#pragma unroll
        for (int b = a + 1; b < PP; b++) {
            float d = zf[a] - zf[b];
            double e = (double)expf(-0.5f * d * d * inv_l2f);
            K[a][b] = e;
            K[b][a] = e;
        }

    // fp64 Cholesky: K = L L^T, keeping invdiag (no divisions)
    double L[PP][PP], invd[PP];
#pragma unroll
    for (int a = 0; a < PP; a++) {
        double s = K[a][a];
        for (int k = 0; k < a; k++) s -= L[a][k] * L[a][k];
        double rs = drsqrt(s);
        L[a][a] = s * rs;
        invd[a] = rs;
        for (int b = a + 1; b < PP; b++) {
            double t = K[b][a];
            for (int k = 0; k < a; k++) t -= L[b][k] * L[a][k];
            L[b][a] = t * rs;
        }
    }

    // Linv (lower triangular inverse of L)
    double Li[PP][PP];
#pragma unroll
    for (int c = 0; c < PP; c++) {
        for (int a = 0; a < PP; a++) {
            if (a < c) { Li[a][c] = 0.0; continue; }
            double t = (a == c) ? 1.0 : 0.0;
            for (int k = c; k < a; k++) t -= L[a][k] * Li[k][c];
            Li[a][c] = t * invd[a];
        }
    }

    // alpha = K^{-1} h via two triangular solves
    double t1[PP];
#pragma unroll
    for (int a = 0; a < PP; a++) {
        double t = hh[a];
        for (int k = 0; k < a; k++) t -= L[a][k] * t1[k];
        t1[a] = t * invd[a];
    }
    double alpha[PP];
    for (int a = PP - 1; a >= 0; a--) {
        double t = t1[a];
        for (int k = a + 1; k < PP; k++) t -= L[k][a] * alpha[k];
        alpha[a] = t * invd[a];
    }

    // Emit 26 duplicated pairs; sqrt(l2) folded into alpha and Linv.
    float vals[26];
    vals[0] = l2f;
#pragma unroll
    for (int p = 0; p < PP; p++) vals[1 + p] = -zf[p];
#pragma unroll
    for (int p = 0; p < PP; p++) vals[6 + p] = lf * (float)alpha[p];
    int k = 11;
#pragma unroll
    for (int a = 0; a < PP; a++)
#pragma unroll
        for (int b = 0; b <= a; b++) vals[k++] = lf * (float)Li[a][b];

    float* pp = &g_params[(i * OC + o) * RECF];
#pragma unroll
    for (int j = 0; j < 26; j++) { pp[2 * j] = vals[j]; pp[2 * j + 1] = vals[j]; }
}

// ---------------------------------------------------------------------------
// Kernel 2: main GP moment propagation, packed f32x2, params in SMEM.
// CTA = 128 threads = 4 warps = ONE output channel x 4 input-channel quarters,
// covering 64 pixels (2 ow-rows packed per thread lane).
// Grid = 128 pixel-groups x 16 channels = 2048 CTAs.
// Per-CTA smem: full param table for its channel (72 x 13 ulonglong2 = 15KB),
// staged once; inner loop reads warp-uniform LDS.128 (off the LDG/LSU path).
// ---------------------------------------------------------------------------
#define TROW 306           // 34 * 9 float2 per tile row
__global__ __launch_bounds__(128) void gp_main(const float* __restrict__ xm,
                                               const float* __restrict__ xv,
                                               float* __restrict__ out)
{
    __shared__ ulonglong2 s_par[IDIM * RECQ];     // 14976 B
    __shared__ float2     s_tile[4 * TROW];       // 9792 B, (m,v) interleaved
    __shared__ u64        red_m[3][32];
    __shared__ u64        red_v[3][32];

    const int tid  = threadIdx.x;
    const int warp = tid >> 5;
    const int lane = tid & 31;

    const int g    = blockIdx.x >> 4;          // 128 pixel groups of 64
    const int o    = blockIdx.x & 15;          // output channel
    const int base = g * 64;
    const int n    = base >> 10;
    const int oh0  = (base >> 5) & 31;         // even

    // ---- stage param table for this o: 72 records x 13 ulonglong2 ----
    {
        const ulonglong2* __restrict__ gp = (const ulonglong2*)g_params;
        for (int j = tid; j < IDIM * RECQ; j += 128) {
            int i = j / RECQ;
            int q = j - i * RECQ;
            s_par[j] = gp[(i * OC + o) * RECQ + q];
        }
    }

    // ---- zero tile, then fill interior rows with float4 gmem loads ----
    for (int j = tid; j < 4 * TROW; j += 128) s_tile[j] = make_float2(0.0f, 0.0f);
    __syncthreads();
    for (int j = tid; j < 4 * 64; j += 128) {
        int t    = j >> 6;                 // tile row 0..3  -> y = oh0-1+t
        int r    = j & 63;
        int x    = r >> 1;
        int half = (r & 1) * 4;
        int y    = oh0 - 1 + t;
        if ((unsigned)y < 32u) {
            const float4 m4 = *(const float4*)&xm[(((n * IHW + y) * IHW + x) * IC) + half];
            const float4 v4 = *(const float4*)&xv[(((n * IHW + y) * IHW + x) * IC) + half];
            int b = t * TROW + (x + 1) * 9 + half;
            s_tile[b + 0] = make_float2(m4.x, v4.x);
            s_tile[b + 1] = make_float2(m4.y, v4.y);
            s_tile[b + 2] = make_float2(m4.z, v4.z);
            s_tile[b + 3] = make_float2(m4.w, v4.w);
        }
    }
    __syncthreads();

    const u64 kneg = pk2(-0.7213475204f, -0.7213475204f);  // -0.5*log2(e)
    u64 accm = 0ull;
    u64 accv = 0ull;

    const float2* __restrict__ bt = s_tile + lane * 9;

#pragma unroll
    for (int cc = 0; cc < 2; cc++) {
        const int c = warp * 2 + cc;       // input channel (warp-uniform)
        const ulonglong2* __restrict__ sp = s_par + c * 9 * RECQ;
#pragma unroll
        for (int k9 = 0; k9 < 9; k9++) {
            const int kh = k9 / 3;
            const int kw = k9 % 3;

            const ulonglong2* pp = sp + k9 * RECQ;
            ulonglong2 v0 = pp[0],  v1 = pp[1],  v2 = pp[2],  v3 = pp[3];
            ulonglong2 v4 = pp[4],  v5 = pp[5],  v6 = pp[6];
            ulonglong2 v7 = pp[7],  v8 = pp[8],  v9 = pp[9],  v10 = pp[10];
            ulonglong2 v11 = pp[11], v12 = pp[12];

            const int off = kh * TROW + kw * 9 + c;
            float2 A = bt[off];            // (m, v) row oh0
            float2 B = bt[off + TROW];     // (m, v) row oh0+1
            u64 mu2 = pk2(A.x, B.x);
            u64 s22 = pk2(A.y, B.y);

            u64 d2    = add2(v0.x, s22);          // l2 + s2
            u64 rs2   = rsqrt_2(d2);              // 1/sqrt(d)
            u64 invd2 = mul2(rs2, rs2);           // 1/d
            u64 cc2   = mul2(kneg, invd2);

            u64 e0, e1, e2, e3, e4, df;
            df = add2(mu2, v0.y); e0 = ex2_2(mul2(mul2(df, df), cc2));
            df = add2(mu2, v1.x); e1 = ex2_2(mul2(mul2(df, df), cc2));
            df = add2(mu2, v1.y); e2 = ex2_2(mul2(mul2(df, df), cc2));
            df = add2(mu2, v2.x); e3 = ex2_2(mul2(mul2(df, df), cc2));
            df = add2(mu2, v2.y); e4 = ex2_2(mul2(mul2(df, df), cc2));

            // mean: rsqrt(d) * (e . alpha')      [alpha' = sqrt(l2)*alpha]
            u64 md = mul2(e0, v3.x);
            md = fma2(e1, v3.y, md);
            md = fma2(e2, v4.x, md);
            md = fma2(e3, v4.y, md);
            md = fma2(e4, v5.x, md);
            accm = fma2(rs2, md, accm);

            // var: (1/d) * || L' e ||^2          [L' = sqrt(l2)*Linv]
            u64 w0 = mul2(v5.y, e0);
            u64 w1 = fma2(v6.y, e1, mul2(v6.x, e0));
            u64 w2 = fma2(v8.x, e2, fma2(v7.y, e1, mul2(v7.x, e0)));
            u64 w3 = fma2(v10.x, e3, fma2(v9.y, e2, fma2(v9.x, e1, mul2(v8.y, e0))));
            u64 w4 = fma2(v12.y, e4, fma2(v12.x, e3,
                     fma2(v11.y, e2, fma2(v11.x, e1, mul2(v10.y, e0)))));
            u64 vd = mul2(w0, w0);
            vd = fma2(w1, w1, vd);
            vd = fma2(w2, w2, vd);
            vd = fma2(w3, w3, vd);
            vd = fma2(w4, w4, vd);
            accv = fma2(invd2, vd, accv);
        }
    }

    // ---- reduce the 4 input-channel quarters, warp 0 writes ----
    if (warp) {
        red_m[warp - 1][lane] = accm;
        red_v[warp - 1][lane] = accv;
    }
    __syncthreads();
    if (warp == 0) {
        accm = add2(accm, add2(red_m[0][lane], add2(red_m[1][lane], red_m[2][lane])));
        accv = add2(accv, add2(red_v[0][lane], add2(red_v[1][lane], red_v[2][lane])));
        float mA, mB, vA, vB;
        upk2(accm, mA, mB);
        upk2(accv, vA, vB);
        const int rowA = base + lane;          // (n, oh0,   lane)
        const int rowB = base + 32 + lane;     // (n, oh0+1, lane)
        out[rowA * OC + o] = mA;
        out[rowB * OC + o] = mB;
        out[NROWS * OC + rowA * OC + o] = fmaxf(72.0f - vA, 1e-6f);
        out[NROWS * OC + rowB * OC + o] = fmaxf(72.0f - vB, 1e-6f);
    }
}

// ---------------------------------------------------------------------------
extern "C" void kernel_launch(void* const* d_in, const int* in_sizes, int n_in,
                              void* d_out, int out_size)
{
    const float* xm    = (const float*)d_in[0];  // x_mean [8,32,32,8]
    const float* xv    = (const float*)d_in[1];  // x_var  [8,32,32,8]
    const float* z     = (const float*)d_in[2];  // [16,72,5]
    const float* h     = (const float*)d_in[3];  // [16,72,5]
    const float* raw_l = (const float*)d_in[4];  // [16,72]
    float* out = (float*)d_out;                  // [mean(131072), var(131072)]

    gp_precompute<<<(OC * IDIM + 127) / 128, 128>>>(z, h, raw_l);
    gp_main<<<2048, 128>>>(xm, xv, out);
}